// round 8
// baseline (speedup 1.0000x reference)
#include <cuda_runtime.h>
#include <cuda_bf16.h>
#include <cstdint>

#define B_ROWS 16384
#define N_DIM  1000
#define N_PAD  1024
#define BM 128
#define BN 256
#define BK 32
#define NITER (N_PAD / BK)   // 32
#define NSTAGE 4
#define SM_STRIDE 40         // 32 + 8 pad: 80B rows, conflict-free ldmatrix phases

// Static device scratch (no allocation): PMb 2MB, Yb 33.5MB
__device__ __nv_bfloat16 g_PMb[N_PAD * N_PAD];
__device__ __nv_bfloat16 g_Yb[(size_t)B_ROWS * N_PAD];

// ---------------- pre-kernels (known good) ----------------
__global__ void pm_kernel(const float* __restrict__ P, const float* __restrict__ M) {
    int idx = blockIdx.x * blockDim.x + threadIdx.x;  // over 1024*1024
    int n = idx >> 10, k = idx & 1023;
    float v = 0.0f;
    if (n < N_DIM && k < N_DIM) v = P[n * N_DIM + k] / M[n];
    g_PMb[idx] = __float2bfloat16_rn(v);
}

struct alignas(16) bf8 { __nv_bfloat16 v[8]; };

__global__ void yb_kernel(const float* __restrict__ Y) {
    int idx = blockIdx.x * blockDim.x + threadIdx.x;  // over 16384*128
    int b = idx >> 7, chunk = idx & 127;
    bf8 o;
    if (chunk < 125) {
        const float4 f0 = *reinterpret_cast<const float4*>(&Y[(size_t)b * N_DIM + chunk * 8]);
        const float4 f1 = *reinterpret_cast<const float4*>(&Y[(size_t)b * N_DIM + chunk * 8 + 4]);
        o.v[0] = __float2bfloat16_rn(f0.x); o.v[1] = __float2bfloat16_rn(f0.y);
        o.v[2] = __float2bfloat16_rn(f0.z); o.v[3] = __float2bfloat16_rn(f0.w);
        o.v[4] = __float2bfloat16_rn(f1.x); o.v[5] = __float2bfloat16_rn(f1.y);
        o.v[6] = __float2bfloat16_rn(f1.z); o.v[7] = __float2bfloat16_rn(f1.w);
    } else {
        #pragma unroll
        for (int i = 0; i < 8; i++) o.v[i] = __float2bfloat16_rn(0.0f);
    }
    *reinterpret_cast<bf8*>(&g_Yb[(size_t)b * N_PAD + chunk * 8]) = o;
}

__global__ void zero_kernel(float* __restrict__ out) {
    int idx = blockIdx.x * blockDim.x + threadIdx.x;
    if (idx < B_ROWS) out[idx] = 0.0f;
}

// ---------------- tensor-core helpers ----------------
__device__ __forceinline__ void ldsm_x4(uint32_t& r0, uint32_t& r1, uint32_t& r2, uint32_t& r3,
                                        const void* sptr) {
    uint32_t addr = (uint32_t)__cvta_generic_to_shared(sptr);
    asm volatile("ldmatrix.sync.aligned.m8n8.x4.shared.b16 {%0,%1,%2,%3}, [%4];"
                 : "=r"(r0), "=r"(r1), "=r"(r2), "=r"(r3) : "r"(addr));
}

__device__ __forceinline__ void mma_bf16(float* c, const uint32_t* a, const uint32_t* b) {
    asm volatile(
        "mma.sync.aligned.m16n8k16.row.col.f32.bf16.bf16.f32 "
        "{%0,%1,%2,%3}, {%4,%5,%6,%7}, {%8,%9}, {%0,%1,%2,%3};"
        : "+f"(c[0]), "+f"(c[1]), "+f"(c[2]), "+f"(c[3])
        : "r"(a[0]), "r"(a[1]), "r"(a[2]), "r"(a[3]), "r"(b[0]), "r"(b[1]));
}

__device__ __forceinline__ void cp_async16(void* sptr, const void* gptr) {
    uint32_t addr = (uint32_t)__cvta_generic_to_shared(sptr);
    asm volatile("cp.async.cg.shared.global [%0], [%1], 16;" :: "r"(addr), "l"(gptr));
}
__device__ __forceinline__ void cp_commit() { asm volatile("cp.async.commit_group;"); }
template <int N> __device__ __forceinline__ void cp_wait() {
    asm volatile("cp.async.wait_group %0;" :: "n"(N));
}

// ---------------- main fused QF kernel ----------------
// losses[b] = (1/1000) * sum_{n,k} Yb[b,n] * PMb[n,k] * Yb[b,k]
// C = Yb @ PMb^T (bf16 mma, fp32 accum), epilogue rowsum(Yb .* C) from fragments.
// CTA 128x256, 8 warps of 64x64 (mma:ldsm = 4:1), 4-stage cp.async, one barrier/iter.
__global__ __launch_bounds__(256, 1) void qf_tc_kernel(float* __restrict__ out) {
    extern __shared__ __nv_bfloat16 dsm[];
    typedef __nv_bfloat16 (*TileA)[BM][SM_STRIDE];
    typedef __nv_bfloat16 (*TileB)[BN][SM_STRIDE];
    TileA As = reinterpret_cast<TileA>(dsm);                                  // [NSTAGE][128][40]
    TileB Bs = reinterpret_cast<TileB>(dsm + NSTAGE * BM * SM_STRIDE);        // [NSTAGE][256][40]

    const int tid  = threadIdx.x;
    const int lane = tid & 31;
    const int w    = tid >> 5;          // 0..7
    const int wm   = w >> 2;            // 0..1  (64 rows each)
    const int wn   = w & 3;             // 0..3  (64 cols each)
    const int g    = lane >> 2;         // group 0..7
    const int tig  = lane & 3;

    const int rowBase = blockIdx.y * BM;
    const int colBase = blockIdx.x * BN;

    // ldmatrix lane mappings (proven)
    const int arow = lane & 15, acol = (lane >> 4) * 8;          // A x4
    const int bt = lane >> 3, brow = lane & 7;                   // B x4
    const int bn_off = (bt >> 1) * 8 + brow, bk_off = (bt & 1) * 8;

    // cp.async mappings
    const int a_row = tid >> 1;          // A: 512 chunks, 2 per thread
    const int a_c0  = (tid & 1) * 2;

    float acc[4][8][4];
    #pragma unroll
    for (int mi = 0; mi < 4; mi++)
        #pragma unroll
        for (int ni = 0; ni < 8; ni++)
            #pragma unroll
            for (int r = 0; r < 4; r++) acc[mi][ni][r] = 0.0f;

    const __nv_bfloat16* Ag = &g_Yb[(size_t)(rowBase + a_row) * N_PAD];

    auto load_stage = [&](int s, int k0) {
        #pragma unroll
        for (int c = 0; c < 2; c++)
            cp_async16(&As[s][a_row][(a_c0 + c) * 8], Ag + k0 + (a_c0 + c) * 8);
        #pragma unroll
        for (int i = 0; i < 4; i++) {        // B: 1024 chunks, 4 per thread
            int cid = tid + i * 256;
            int r = cid >> 2, c = cid & 3;
            cp_async16(&Bs[s][r][c * 8],
                       &g_PMb[(size_t)(colBase + r) * N_PAD + k0 + c * 8]);
        }
    };

    // prologue: stages 0,1,2 (one commit group each)
    #pragma unroll
    for (int s = 0; s < NSTAGE - 1; s++) {
        load_stage(s, s * BK);
        cp_commit();
    }

    for (int it = 0; it < NITER; it++) {
        const int cur = it & (NSTAGE - 1);
        cp_wait<2>();
        __syncthreads();   // all warps done with it-1 -> safe to refill (it+3)&3

        if (it + NSTAGE - 1 < NITER)
            load_stage((it + NSTAGE - 1) & (NSTAGE - 1), (it + NSTAGE - 1) * BK);
        cp_commit();       // unconditional: uniform group accounting

        #pragma unroll
        for (int ks = 0; ks < 2; ks++) {
            uint32_t a[4][4], b[8][2];
            #pragma unroll
            for (int mi = 0; mi < 4; mi++)
                ldsm_x4(a[mi][0], a[mi][1], a[mi][2], a[mi][3],
                        &As[cur][wm * 64 + mi * 16 + arow][ks * 16 + acol]);
            #pragma unroll
            for (int j = 0; j < 4; j++)
                ldsm_x4(b[2 * j][0], b[2 * j][1], b[2 * j + 1][0], b[2 * j + 1][1],
                        &Bs[cur][wn * 64 + j * 16 + bn_off][ks * 16 + bk_off]);
            #pragma unroll
            for (int mi = 0; mi < 4; mi++)
                #pragma unroll
                for (int ni = 0; ni < 8; ni++)
                    mma_bf16(acc[mi][ni], a[mi], b[ni]);
        }
    }

    // Epilogue: partial[b] += sum_col acc * Yb[b, col]; reduce over tig; atomicAdd
    const float invN = 1.0f / (float)N_DIM;
    #pragma unroll
    for (int mi = 0; mi < 4; mi++) {
        const int row0 = rowBase + wm * 64 + mi * 16 + g;   // and row0+8
        float p0 = 0.0f, p1 = 0.0f;
        #pragma unroll
        for (int ni = 0; ni < 8; ni++) {
            const int col = colBase + wn * 64 + ni * 8 + tig * 2;
            const uint32_t y0 = *reinterpret_cast<const uint32_t*>(
                &g_Yb[(size_t)row0 * N_PAD + col]);
            const uint32_t y1 = *reinterpret_cast<const uint32_t*>(
                &g_Yb[(size_t)(row0 + 8) * N_PAD + col]);
            const float y0a = __uint_as_float(y0 << 16);
            const float y0b = __uint_as_float(y0 & 0xffff0000u);
            const float y1a = __uint_as_float(y1 << 16);
            const float y1b = __uint_as_float(y1 & 0xffff0000u);
            p0 += acc[mi][ni][0] * y0a + acc[mi][ni][1] * y0b;
            p1 += acc[mi][ni][2] * y1a + acc[mi][ni][3] * y1b;
        }
        #pragma unroll
        for (int off = 1; off <= 2; off <<= 1) {
            p0 += __shfl_xor_sync(0xffffffffu, p0, off);
            p1 += __shfl_xor_sync(0xffffffffu, p1, off);
        }
        if (tig == 0) {
            atomicAdd(&out[row0], p0 * invN);
            atomicAdd(&out[row0 + 8], p1 * invN);
        }
    }
}

#define QF_SMEM_BYTES (NSTAGE * (BM + BN) * SM_STRIDE * (int)sizeof(__nv_bfloat16))  // 122880

extern "C" void kernel_launch(void* const* d_in, const int* in_sizes, int n_in,
                              void* d_out, int out_size) {
    const float* y_pred = (const float*)d_in[0];
    // d_in[1] = y_true (unused)
    const float* P = (const float*)d_in[2];
    const float* M = (const float*)d_in[3];
    float* out = (float*)d_out;
    (void)in_sizes; (void)n_in; (void)out_size;

    cudaFuncSetAttribute(qf_tc_kernel,
                         cudaFuncAttributeMaxDynamicSharedMemorySize, QF_SMEM_BYTES);

    pm_kernel<<<(N_PAD * N_PAD) / 256, 256>>>(P, M);
    yb_kernel<<<(B_ROWS * (N_PAD / 8)) / 256, 256>>>(y_pred);
    zero_kernel<<<B_ROWS / 256, 256>>>(out);

    dim3 grid(N_PAD / BN, B_ROWS / BM);   // (4, 128)
    qf_tc_kernel<<<grid, 256, QF_SMEM_BYTES>>>(out);
}

// round 9
// speedup vs baseline: 1.0002x; 1.0002x over previous
#include <cuda_runtime.h>
#include <cuda_bf16.h>
#include <cstdint>

#define B_ROWS 16384
#define N_DIM  1000
#define N_PAD  1024
#define BM 128
#define BN 256
#define BK 32
#define NITER (N_PAD / BK)   // 32
#define NSTAGE 4
#define SM_STRIDE 40         // 32 + 8 pad: 80B rows, conflict-free ldmatrix phases

// Static device scratch (no allocation): PMb 2MB, Yb 33.5MB
__device__ __nv_bfloat16 g_PMb[N_PAD * N_PAD];
__device__ __nv_bfloat16 g_Yb[(size_t)B_ROWS * N_PAD];

// ---------------- pre-kernels (known good) ----------------
__global__ void pm_kernel(const float* __restrict__ P, const float* __restrict__ M) {
    int idx = blockIdx.x * blockDim.x + threadIdx.x;  // over 1024*1024
    int n = idx >> 10, k = idx & 1023;
    float v = 0.0f;
    if (n < N_DIM && k < N_DIM) v = P[n * N_DIM + k] / M[n];
    g_PMb[idx] = __float2bfloat16_rn(v);
}

struct alignas(16) bf8 { __nv_bfloat16 v[8]; };

__global__ void yb_kernel(const float* __restrict__ Y) {
    int idx = blockIdx.x * blockDim.x + threadIdx.x;  // over 16384*128
    int b = idx >> 7, chunk = idx & 127;
    bf8 o;
    if (chunk < 125) {
        const float4 f0 = *reinterpret_cast<const float4*>(&Y[(size_t)b * N_DIM + chunk * 8]);
        const float4 f1 = *reinterpret_cast<const float4*>(&Y[(size_t)b * N_DIM + chunk * 8 + 4]);
        o.v[0] = __float2bfloat16_rn(f0.x); o.v[1] = __float2bfloat16_rn(f0.y);
        o.v[2] = __float2bfloat16_rn(f0.z); o.v[3] = __float2bfloat16_rn(f0.w);
        o.v[4] = __float2bfloat16_rn(f1.x); o.v[5] = __float2bfloat16_rn(f1.y);
        o.v[6] = __float2bfloat16_rn(f1.z); o.v[7] = __float2bfloat16_rn(f1.w);
    } else {
        #pragma unroll
        for (int i = 0; i < 8; i++) o.v[i] = __float2bfloat16_rn(0.0f);
    }
    *reinterpret_cast<bf8*>(&g_Yb[(size_t)b * N_PAD + chunk * 8]) = o;
}

__global__ void zero_kernel(float* __restrict__ out) {
    int idx = blockIdx.x * blockDim.x + threadIdx.x;
    if (idx < B_ROWS) out[idx] = 0.0f;
}

// ---------------- tensor-core helpers ----------------
__device__ __forceinline__ void ldsm_x4(uint32_t& r0, uint32_t& r1, uint32_t& r2, uint32_t& r3,
                                        const void* sptr) {
    uint32_t addr = (uint32_t)__cvta_generic_to_shared(sptr);
    asm volatile("ldmatrix.sync.aligned.m8n8.x4.shared.b16 {%0,%1,%2,%3}, [%4];"
                 : "=r"(r0), "=r"(r1), "=r"(r2), "=r"(r3) : "r"(addr));
}

__device__ __forceinline__ void mma_bf16(float* c, const uint32_t* a, const uint32_t* b) {
    asm volatile(
        "mma.sync.aligned.m16n8k16.row.col.f32.bf16.bf16.f32 "
        "{%0,%1,%2,%3}, {%4,%5,%6,%7}, {%8,%9}, {%0,%1,%2,%3};"
        : "+f"(c[0]), "+f"(c[1]), "+f"(c[2]), "+f"(c[3])
        : "r"(a[0]), "r"(a[1]), "r"(a[2]), "r"(a[3]), "r"(b[0]), "r"(b[1]));
}

__device__ __forceinline__ void cp_async16(void* sptr, const void* gptr) {
    uint32_t addr = (uint32_t)__cvta_generic_to_shared(sptr);
    asm volatile("cp.async.cg.shared.global [%0], [%1], 16;" :: "r"(addr), "l"(gptr));
}
__device__ __forceinline__ void cp_commit() { asm volatile("cp.async.commit_group;"); }
template <int N> __device__ __forceinline__ void cp_wait() {
    asm volatile("cp.async.wait_group %0;" :: "n"(N));
}

// ---------------- main fused QF kernel ----------------
// losses[b] = (1/1000) * sum_{n,k} Yb[b,n] * PMb[n,k] * Yb[b,k]
// C = Yb @ PMb^T (bf16 mma, fp32 accum), epilogue rowsum(Yb .* C) from fragments.
// CTA 128x256, 8 warps of 64x64 (mma:ldsm = 4:1), 4-stage cp.async, one barrier/iter.
__global__ __launch_bounds__(256, 1) void qf_tc_kernel(float* __restrict__ out) {
    extern __shared__ __nv_bfloat16 dsm[];
    typedef __nv_bfloat16 (*TileA)[BM][SM_STRIDE];
    typedef __nv_bfloat16 (*TileB)[BN][SM_STRIDE];
    TileA As = reinterpret_cast<TileA>(dsm);                                  // [NSTAGE][128][40]
    TileB Bs = reinterpret_cast<TileB>(dsm + NSTAGE * BM * SM_STRIDE);        // [NSTAGE][256][40]

    const int tid  = threadIdx.x;
    const int lane = tid & 31;
    const int w    = tid >> 5;          // 0..7
    const int wm   = w >> 2;            // 0..1  (64 rows each)
    const int wn   = w & 3;             // 0..3  (64 cols each)
    const int g    = lane >> 2;         // group 0..7
    const int tig  = lane & 3;

    const int rowBase = blockIdx.y * BM;
    const int colBase = blockIdx.x * BN;

    // ldmatrix lane mappings (proven)
    const int arow = lane & 15, acol = (lane >> 4) * 8;          // A x4
    const int bt = lane >> 3, brow = lane & 7;                   // B x4
    const int bn_off = (bt >> 1) * 8 + brow, bk_off = (bt & 1) * 8;

    // cp.async mappings
    const int a_row = tid >> 1;          // A: 512 chunks, 2 per thread
    const int a_c0  = (tid & 1) * 2;

    float acc[4][8][4];
    #pragma unroll
    for (int mi = 0; mi < 4; mi++)
        #pragma unroll
        for (int ni = 0; ni < 8; ni++)
            #pragma unroll
            for (int r = 0; r < 4; r++) acc[mi][ni][r] = 0.0f;

    const __nv_bfloat16* Ag = &g_Yb[(size_t)(rowBase + a_row) * N_PAD];

    auto load_stage = [&](int s, int k0) {
        #pragma unroll
        for (int c = 0; c < 2; c++)
            cp_async16(&As[s][a_row][(a_c0 + c) * 8], Ag + k0 + (a_c0 + c) * 8);
        #pragma unroll
        for (int i = 0; i < 4; i++) {        // B: 1024 chunks, 4 per thread
            int cid = tid + i * 256;
            int r = cid >> 2, c = cid & 3;
            cp_async16(&Bs[s][r][c * 8],
                       &g_PMb[(size_t)(colBase + r) * N_PAD + k0 + c * 8]);
        }
    };

    // prologue: stages 0,1,2 (one commit group each)
    #pragma unroll
    for (int s = 0; s < NSTAGE - 1; s++) {
        load_stage(s, s * BK);
        cp_commit();
    }

    for (int it = 0; it < NITER; it++) {
        const int cur = it & (NSTAGE - 1);
        cp_wait<2>();
        __syncthreads();   // all warps done with it-1 -> safe to refill (it+3)&3

        if (it + NSTAGE - 1 < NITER)
            load_stage((it + NSTAGE - 1) & (NSTAGE - 1), (it + NSTAGE - 1) * BK);
        cp_commit();       // unconditional: uniform group accounting

        #pragma unroll
        for (int ks = 0; ks < 2; ks++) {
            uint32_t a[4][4], b[8][2];
            #pragma unroll
            for (int mi = 0; mi < 4; mi++)
                ldsm_x4(a[mi][0], a[mi][1], a[mi][2], a[mi][3],
                        &As[cur][wm * 64 + mi * 16 + arow][ks * 16 + acol]);
            #pragma unroll
            for (int j = 0; j < 4; j++)
                ldsm_x4(b[2 * j][0], b[2 * j][1], b[2 * j + 1][0], b[2 * j + 1][1],
                        &Bs[cur][wn * 64 + j * 16 + bn_off][ks * 16 + bk_off]);
            #pragma unroll
            for (int mi = 0; mi < 4; mi++)
                #pragma unroll
                for (int ni = 0; ni < 8; ni++)
                    mma_bf16(acc[mi][ni], a[mi], b[ni]);
        }
    }

    // Epilogue: partial[b] += sum_col acc * Yb[b, col]; reduce over tig; atomicAdd
    const float invN = 1.0f / (float)N_DIM;
    #pragma unroll
    for (int mi = 0; mi < 4; mi++) {
        const int row0 = rowBase + wm * 64 + mi * 16 + g;   // and row0+8
        float p0 = 0.0f, p1 = 0.0f;
        #pragma unroll
        for (int ni = 0; ni < 8; ni++) {
            const int col = colBase + wn * 64 + ni * 8 + tig * 2;
            const uint32_t y0 = *reinterpret_cast<const uint32_t*>(
                &g_Yb[(size_t)row0 * N_PAD + col]);
            const uint32_t y1 = *reinterpret_cast<const uint32_t*>(
                &g_Yb[(size_t)(row0 + 8) * N_PAD + col]);
            const float y0a = __uint_as_float(y0 << 16);
            const float y0b = __uint_as_float(y0 & 0xffff0000u);
            const float y1a = __uint_as_float(y1 << 16);
            const float y1b = __uint_as_float(y1 & 0xffff0000u);
            p0 += acc[mi][ni][0] * y0a + acc[mi][ni][1] * y0b;
            p1 += acc[mi][ni][2] * y1a + acc[mi][ni][3] * y1b;
        }
        #pragma unroll
        for (int off = 1; off <= 2; off <<= 1) {
            p0 += __shfl_xor_sync(0xffffffffu, p0, off);
            p1 += __shfl_xor_sync(0xffffffffu, p1, off);
        }
        if (tig == 0) {
            atomicAdd(&out[row0], p0 * invN);
            atomicAdd(&out[row0 + 8], p1 * invN);
        }
    }
}

#define QF_SMEM_BYTES (NSTAGE * (BM + BN) * SM_STRIDE * (int)sizeof(__nv_bfloat16))  // 122880

extern "C" void kernel_launch(void* const* d_in, const int* in_sizes, int n_in,
                              void* d_out, int out_size) {
    const float* y_pred = (const float*)d_in[0];
    // d_in[1] = y_true (unused)
    const float* P = (const float*)d_in[2];
    const float* M = (const float*)d_in[3];
    float* out = (float*)d_out;
    (void)in_sizes; (void)n_in; (void)out_size;

    cudaFuncSetAttribute(qf_tc_kernel,
                         cudaFuncAttributeMaxDynamicSharedMemorySize, QF_SMEM_BYTES);

    pm_kernel<<<(N_PAD * N_PAD) / 256, 256>>>(P, M);
    yb_kernel<<<(B_ROWS * (N_PAD / 8)) / 256, 256>>>(y_pred);
    zero_kernel<<<B_ROWS / 256, 256>>>(out);

    dim3 grid(N_PAD / BN, B_ROWS / BM);   // (4, 128)
    qf_tc_kernel<<<grid, 256, QF_SMEM_BYTES>>>(out);
}